// round 12
// baseline (speedup 1.0000x reference)
#include <cuda_runtime.h>
#include <cuda_bf16.h>
#include <cstdint>
#include <math.h>

#define H       1024
#define BATCH   4
#define SEQ     2048
#define M_ALL   (BATCH * SEQ)

// ---------------------------------------------------------------------------
// Tiling: CTA 128x128, K-chunk 32, 16 warps (4 rows x 4 cols), warp tile 32x32
// 3-stage cp.async pipeline, one __syncthreads per chunk.
// ---------------------------------------------------------------------------
constexpr int RB          = 80;                // smem bytes/row (64B data + 16B pad)
constexpr int TILE_BYTES  = 128 * RB;          // 10240
constexpr int STAGE_BYTES = 4 * TILE_BYTES;    // Ah, Al, Bh, Bl
constexpr int NSTAGE      = 3;
constexpr int SMEM_BYTES  = NSTAGE * STAGE_BYTES;  // 122880
constexpr int SF          = 132;               // epilogue f32 row stride

// ---------------------------------------------------------------------------
// PTX helpers (sm_103 baseline ISA only: ldmatrix / mma.sync / cp.async)
// ---------------------------------------------------------------------------
__device__ __forceinline__ uint32_t smem_to_u32(const void* p) {
    uint32_t a;
    asm("{ .reg .u64 t; cvta.to.shared.u64 t, %1; cvt.u32.u64 %0, t; }" : "=r"(a) : "l"(p));
    return a;
}

#define CP_ASYNC16(dst, src) \
    asm volatile("cp.async.cg.shared.global [%0], [%1], 16;" :: "r"(dst), "l"(src))
#define CP_COMMIT() asm volatile("cp.async.commit_group;" ::: "memory")
#define CP_WAIT(n)  asm volatile("cp.async.wait_group %0;" :: "n"(n) : "memory")

#define LDSM_X4(r0, r1, r2, r3, addr) \
    asm volatile("ldmatrix.sync.aligned.m8n8.x4.shared.b16 {%0,%1,%2,%3}, [%4];" \
        : "=r"(r0), "=r"(r1), "=r"(r2), "=r"(r3) : "r"(addr))

__device__ __forceinline__ void mma16816(float* c, const uint32_t* a,
                                         uint32_t b0, uint32_t b1) {
    asm volatile(
        "mma.sync.aligned.m16n8k16.row.col.f32.bf16.bf16.f32 "
        "{%0,%1,%2,%3}, {%4,%5,%6,%7}, {%8,%9}, {%0,%1,%2,%3};"
        : "+f"(c[0]), "+f"(c[1]), "+f"(c[2]), "+f"(c[3])
        : "r"(a[0]), "r"(a[1]), "r"(a[2]), "r"(a[3]), "r"(b0), "r"(b1));
}

// ---------------------------------------------------------------------------
// Scratch (device globals; allocation-free)
// ---------------------------------------------------------------------------
__device__ __align__(256) __nv_bfloat16 g_Xh[(size_t)M_ALL * H];
__device__ __align__(256) __nv_bfloat16 g_Xl[(size_t)M_ALL * H];
__device__ __align__(256) __nv_bfloat16 g_Wh[3 * (size_t)H * H];
__device__ __align__(256) __nv_bfloat16 g_Wl[3 * (size_t)H * H];
__device__ __align__(256) __nv_bfloat16 g_Qh[(size_t)M_ALL * H];
__device__ __align__(256) __nv_bfloat16 g_Ql[(size_t)M_ALL * H];
__device__ __align__(256) __nv_bfloat16 g_Kh[(size_t)M_ALL * H];
__device__ __align__(256) __nv_bfloat16 g_Kl[(size_t)M_ALL * H];
__device__ __align__(256) __nv_bfloat16 g_Vth[(size_t)BATCH * H * SEQ];  // [b][h][s]
__device__ __align__(256) __nv_bfloat16 g_Vtl[(size_t)BATCH * H * SEQ];
__device__ __align__(256) float         g_S [(size_t)BATCH * SEQ * SEQ];
__device__ __align__(256) __nv_bfloat16 g_Ph[(size_t)BATCH * SEQ * SEQ];
__device__ __align__(256) __nv_bfloat16 g_Pl[(size_t)BATCH * SEQ * SEQ];

// ---------------------------------------------------------------------------
// Stage one 128x32 bf16 tile (K-contiguous rows) into padded smem via cp.async
// 512 threads: exactly one 16B copy per thread per tile.
// ---------------------------------------------------------------------------
__device__ __forceinline__ void stage_in(const __nv_bfloat16* __restrict__ g,
                                         size_t ld, int k0, uint32_t dst, int tid) {
    const int row = tid >> 2, c = tid & 3;
    const __nv_bfloat16* src = g + (size_t)row * ld + k0 + c * 8;
    CP_ASYNC16(dst + row * RB + c * 16, src);
}

__device__ __forceinline__ void stage_all(const __nv_bfloat16* Ah, const __nv_bfloat16* Al,
                                          size_t lda,
                                          const __nv_bfloat16* Bh, const __nv_bfloat16* Bl,
                                          size_t ldb, int k0, uint32_t sb, int tid) {
    stage_in(Ah, lda, k0, sb + 0 * TILE_BYTES, tid);
    stage_in(Al, lda, k0, sb + 1 * TILE_BYTES, tid);
    stage_in(Bh, ldb, k0, sb + 2 * TILE_BYTES, tid);
    stage_in(Bl, ldb, k0, sb + 3 * TILE_BYTES, tid);
    CP_COMMIT();
}

// ---------------------------------------------------------------------------
// Compute one 32-wide K-chunk from a resident stage: 2 k16 steps x 3 products
// Warp tile 32x32: mt in {0,1}, nt in {0..3}.
// ---------------------------------------------------------------------------
__device__ __forceinline__ void compute_stage(uint32_t st_base, uint32_t aByte,
                                              uint32_t bByte, float (&acc)[2][4][4]) {
#pragma unroll
    for (int ks = 0; ks < 2; ks++) {
        uint32_t ah[2][4], al[2][4], bh[2][4], bl[2][4];
#pragma unroll
        for (int np = 0; np < 2; np++) {
            uint32_t bo = st_base + bByte + np * 16 * RB + ks * 32;
            LDSM_X4(bh[np][0], bh[np][1], bh[np][2], bh[np][3], bo + 2 * TILE_BYTES);
            LDSM_X4(bl[np][0], bl[np][1], bl[np][2], bl[np][3], bo + 3 * TILE_BYTES);
        }
#pragma unroll
        for (int mt = 0; mt < 2; mt++) {
            uint32_t ao = st_base + aByte + mt * 16 * RB + ks * 32;
            LDSM_X4(ah[mt][0], ah[mt][1], ah[mt][2], ah[mt][3], ao + 0 * TILE_BYTES);
            LDSM_X4(al[mt][0], al[mt][1], al[mt][2], al[mt][3], ao + 1 * TILE_BYTES);
        }
#pragma unroll
        for (int mt = 0; mt < 2; mt++)
#pragma unroll
            for (int nt = 0; nt < 4; nt++) {
                const uint32_t b0h = bh[nt >> 1][(nt & 1) * 2];
                const uint32_t b1h = bh[nt >> 1][(nt & 1) * 2 + 1];
                const uint32_t b0l = bl[nt >> 1][(nt & 1) * 2];
                const uint32_t b1l = bl[nt >> 1][(nt & 1) * 2 + 1];
                mma16816(acc[mt][nt], ah[mt], b0h, b1h);
                mma16816(acc[mt][nt], ah[mt], b0l, b1l);
                mma16816(acc[mt][nt], al[mt], b0h, b1h);
            }
    }
}

// ---------------------------------------------------------------------------
// Full mainloop: D(128x128 f32, in registers) = AhBh + AhBl + AlBh over Kdim
// 3-stage pipeline, prefetch distance 2, ONE __syncthreads per chunk.
// ---------------------------------------------------------------------------
__device__ __forceinline__ void gemm_core(const __nv_bfloat16* Ah, const __nv_bfloat16* Al,
                                          size_t lda,
                                          const __nv_bfloat16* Bh, const __nv_bfloat16* Bl,
                                          size_t ldb, int Kdim, uint32_t sbase, int tid,
                                          float (&acc)[2][4][4]) {
    const int lane = tid & 31, wid = tid >> 5;
    const int wr = wid >> 2, wc = wid & 3;   // 4x4 warp grid
    // ldmatrix per-lane base offsets (A: m = lane%16, kblk = lane/16;
    //                                 B: n = lane%8 + 8*((lane/16)&1), kblk = (lane/8)&1)
    const uint32_t aByte = sbase + (uint32_t)((wr * 32 + (lane & 15)) * RB + (lane >> 4) * 16);
    const uint32_t bByte = sbase + (uint32_t)((wc * 32 + (lane & 7) + ((lane >> 4) & 1) * 8) * RB
                                              + ((lane >> 3) & 1) * 16);

    const int nch = Kdim / 32;
    // prologue: chunks 0 and 1 into stages 0 and 1 (groups #0, #1)
    stage_all(Ah, Al, lda, Bh, Bl, ldb, 0,  sbase + 0 * STAGE_BYTES, tid);
    stage_all(Ah, Al, lda, Bh, Bl, ldb, 32, sbase + 1 * STAGE_BYTES, tid);

    int ld_stage = 2;   // stage receiving chunk c+2
    int cm_stage = 0;   // stage holding chunk c
#pragma unroll 1
    for (int c = 0; c < nch; c++) {
        CP_WAIT(1);
        __syncthreads();
        if (c + 2 < nch) {
            stage_all(Ah, Al, lda, Bh, Bl, ldb, (c + 2) * 32,
                      sbase + (uint32_t)(ld_stage * STAGE_BYTES), tid);
        } else {
            CP_COMMIT();   // empty group keeps wait_group arithmetic exact
        }
        ld_stage = (ld_stage == NSTAGE - 1) ? 0 : ld_stage + 1;
        compute_stage((uint32_t)(cm_stage * STAGE_BYTES), aByte, bByte, acc);
        cm_stage = (cm_stage == NSTAGE - 1) ? 0 : cm_stage + 1;
    }
    CP_WAIT(0);
    __syncthreads();
}

// Scatter warp accumulators into a 128x128 f32 smem tile (stride SF)
__device__ __forceinline__ void acc_to_smem(float (&acc)[2][4][4], float* smf, int tid) {
    const int lane = tid & 31, wid = tid >> 5;
    const int wr = wid >> 2, wc = wid & 3;
    const int g = lane >> 2, t = lane & 3;
#pragma unroll
    for (int mt = 0; mt < 2; mt++)
#pragma unroll
        for (int nt = 0; nt < 4; nt++) {
            const int m = wr * 32 + mt * 16 + g;
            const int n = wc * 32 + nt * 8 + 2 * t;
            *reinterpret_cast<float2*>(&smf[m * SF + n]) =
                make_float2(acc[mt][nt][0], acc[mt][nt][1]);
            *reinterpret_cast<float2*>(&smf[(m + 8) * SF + n]) =
                make_float2(acc[mt][nt][2], acc[mt][nt][3]);
        }
}

// ---------------------------------------------------------------------------
// Kernel: fp32 -> (hi, lo) bf16 split
// ---------------------------------------------------------------------------
__global__ void split_kernel(const float* __restrict__ src,
                             __nv_bfloat16* __restrict__ dh,
                             __nv_bfloat16* __restrict__ dl, int n4) {
    int i = blockIdx.x * blockDim.x + threadIdx.x;
    if (i >= n4) return;
    float4 v = reinterpret_cast<const float4*>(src)[i];
    float vv[4] = {v.x, v.y, v.z, v.w};
    __nv_bfloat16 hh[4], ll[4];
#pragma unroll
    for (int j = 0; j < 4; j++) {
        hh[j] = __float2bfloat16(vv[j]);
        ll[j] = __float2bfloat16(vv[j] - __bfloat162float(hh[j]));
    }
    reinterpret_cast<__nv_bfloat162*>(dh)[2 * i]     = __halves2bfloat162(hh[0], hh[1]);
    reinterpret_cast<__nv_bfloat162*>(dh)[2 * i + 1] = __halves2bfloat162(hh[2], hh[3]);
    reinterpret_cast<__nv_bfloat162*>(dl)[2 * i]     = __halves2bfloat162(ll[0], ll[1]);
    reinterpret_cast<__nv_bfloat162*>(dl)[2 * i + 1] = __halves2bfloat162(ll[2], ll[3]);
}

// ---------------------------------------------------------------------------
// Kernel 1: QKV projection.  z=0 -> Q (split), z=1 -> K (split), z=2 -> V^T
// grid = (H/128, M_ALL/128, 3), block = 512
// ---------------------------------------------------------------------------
__global__ void __launch_bounds__(512, 1)
qkv_kernel(const float* __restrict__ bq, const float* __restrict__ bk,
           const float* __restrict__ bv) {
    extern __shared__ char sm[];
    const uint32_t sbase = smem_to_u32(sm);
    const int tid = threadIdx.x;
    const int z = blockIdx.z;
    const int m0 = blockIdx.y * 128, n0 = blockIdx.x * 128;

    const __nv_bfloat16* Ah = g_Xh + (size_t)m0 * H;
    const __nv_bfloat16* Al = g_Xl + (size_t)m0 * H;
    const __nv_bfloat16* Bh = g_Wh + (size_t)z * H * H + (size_t)n0 * H;
    const __nv_bfloat16* Bl = g_Wl + (size_t)z * H * H + (size_t)n0 * H;
    const float* bias = (z == 0) ? bq : (z == 1) ? bk : bv;

    float acc[2][4][4] = {};
    gemm_core(Ah, Al, H, Bh, Bl, H, H, sbase, tid, acc);

    float* smf = reinterpret_cast<float*>(sm);
    acc_to_smem(acc, smf, tid);
    __syncthreads();

    if (z < 2) {
        __nv_bfloat16* outH = (z == 0) ? g_Qh : g_Kh;
        __nv_bfloat16* outL = (z == 0) ? g_Ql : g_Kl;
        const int row = tid >> 2, ch = (tid & 3) * 32;
        const size_t go = (size_t)(m0 + row) * H + n0 + ch;
#pragma unroll
        for (int q = 0; q < 4; q++) {
            uint32_t ph[4], pl[4];
#pragma unroll
            for (int j = 0; j < 4; j++) {
                const int n = ch + q * 8 + 2 * j;
                float c0 = smf[row * SF + n]     + bias[n0 + n];
                float c1 = smf[row * SF + n + 1] + bias[n0 + n + 1];
                __nv_bfloat16 h0 = __float2bfloat16(c0), h1 = __float2bfloat16(c1);
                __nv_bfloat16 l0 = __float2bfloat16(c0 - __bfloat162float(h0));
                __nv_bfloat16 l1 = __float2bfloat16(c1 - __bfloat162float(h1));
                __nv_bfloat162 vh = __halves2bfloat162(h0, h1);
                __nv_bfloat162 vl = __halves2bfloat162(l0, l1);
                ph[j] = *reinterpret_cast<uint32_t*>(&vh);
                pl[j] = *reinterpret_cast<uint32_t*>(&vl);
            }
            *reinterpret_cast<uint4*>(outH + go + q * 8) = *reinterpret_cast<const uint4*>(ph);
            *reinterpret_cast<uint4*>(outL + go + q * 8) = *reinterpret_cast<const uint4*>(pl);
        }
    } else {
        // V transposed: Vt[b][n][s]; threads map to s -> coalesced stores
        const int b = m0 >> 11;
        const int s0 = m0 & 2047;
        const int sl = tid & 127, nh = (tid >> 7) * 32;
#pragma unroll 1
        for (int j = 0; j < 32; j++) {
            const int nl = nh + j;
            float c = smf[sl * SF + nl] + bias[n0 + nl];
            __nv_bfloat16 hv = __float2bfloat16(c);
            __nv_bfloat16 lv = __float2bfloat16(c - __bfloat162float(hv));
            const size_t a = (size_t)b * H * SEQ + (size_t)(n0 + nl) * SEQ + s0 + sl;
            g_Vth[a] = hv;
            g_Vtl[a] = lv;
        }
    }
}

// ---------------------------------------------------------------------------
// Kernel 2: scores S = mask ? (Q.K^T)/32 : -inf.  grid = (16, 16, 4), block 512
// ---------------------------------------------------------------------------
__global__ void __launch_bounds__(512, 1)
scores_kernel(const int* __restrict__ mask) {
    extern __shared__ char sm[];
    const uint32_t sbase = smem_to_u32(sm);
    const int tid = threadIdx.x;
    const int b = blockIdx.z;
    const int m0 = blockIdx.y * 128, n0 = blockIdx.x * 128;

    const size_t rowA = (size_t)(b * SEQ + m0) * H;
    const size_t rowB = (size_t)(b * SEQ + n0) * H;

    float acc[2][4][4] = {};
    gemm_core(g_Qh + rowA, g_Ql + rowA, H, g_Kh + rowB, g_Kl + rowB, H, H,
              sbase, tid, acc);

    float* smf = reinterpret_cast<float*>(sm);
    acc_to_smem(acc, smf, tid);
    __syncthreads();

    const float scale = 0.03125f;  // 1/sqrt(1024)
    const int ql = tid >> 2, ch = (tid & 3) * 32;
    const size_t base = ((size_t)(b * SEQ + m0 + ql)) * SEQ + n0 + ch;
    const int4* mk4 = reinterpret_cast<const int4*>(mask + base);
    float4* dst = reinterpret_cast<float4*>(g_S + base);
#pragma unroll
    for (int j4 = 0; j4 < 8; j4++) {
        float4 v = *reinterpret_cast<const float4*>(&smf[ql * SF + ch + j4 * 4]);
        int4 mk = mk4[j4];
        v.x = mk.x ? v.x * scale : -INFINITY;
        v.y = mk.y ? v.y * scale : -INFINITY;
        v.z = mk.z ? v.z * scale : -INFINITY;
        v.w = mk.w ? v.w * scale : -INFINITY;
        dst[j4] = v;
    }
}

// ---------------------------------------------------------------------------
// Kernel 3: row softmax, fp32 in -> split-bf16 P out.  grid = B*S, block 256
// ---------------------------------------------------------------------------
__global__ void softmax_kernel() {
    const size_t row = (size_t)blockIdx.x * SEQ;
    const float* Srow = g_S + row;
    const int tid = threadIdx.x;

    float v[8];
    float m = -INFINITY;
#pragma unroll
    for (int i = 0; i < 8; i++) {
        v[i] = Srow[i * 256 + tid];
        m = fmaxf(m, v[i]);
    }
#pragma unroll
    for (int o = 16; o > 0; o >>= 1) m = fmaxf(m, __shfl_xor_sync(0xffffffffu, m, o));
    __shared__ float smax[8];
    if ((tid & 31) == 0) smax[tid >> 5] = m;
    __syncthreads();
    float mm = smax[0];
#pragma unroll
    for (int i = 1; i < 8; i++) mm = fmaxf(mm, smax[i]);

    float s = 0.f;
#pragma unroll
    for (int i = 0; i < 8; i++) { v[i] = __expf(v[i] - mm); s += v[i]; }
#pragma unroll
    for (int o = 16; o > 0; o >>= 1) s += __shfl_xor_sync(0xffffffffu, s, o);
    __shared__ float ssum[8];
    if ((tid & 31) == 0) ssum[tid >> 5] = s;
    __syncthreads();
    float tot = 0.f;
#pragma unroll
    for (int i = 0; i < 8; i++) tot += ssum[i];
    const float inv = 1.0f / tot;
#pragma unroll
    for (int i = 0; i < 8; i++) {
        float p = v[i] * inv;
        __nv_bfloat16 h = __float2bfloat16(p);
        __nv_bfloat16 l = __float2bfloat16(p - __bfloat162float(h));
        g_Ph[row + i * 256 + tid] = h;
        g_Pl[row + i * 256 + tid] = l;
    }
}

// ---------------------------------------------------------------------------
// Kernel 4: out = P @ V (NT vs V^T).  grid = (H/128, SEQ/128, 4), block 512
// ---------------------------------------------------------------------------
__global__ void __launch_bounds__(512, 1)
pv_kernel(float* __restrict__ out) {
    extern __shared__ char sm[];
    const uint32_t sbase = smem_to_u32(sm);
    const int tid = threadIdx.x;
    const int b = blockIdx.z;
    const int m0 = blockIdx.y * 128, n0 = blockIdx.x * 128;

    const size_t rowA = ((size_t)b * SEQ + m0) * SEQ;
    const size_t rowB = (size_t)b * H * SEQ + (size_t)n0 * SEQ;

    float acc[2][4][4] = {};
    gemm_core(g_Ph + rowA, g_Pl + rowA, SEQ, g_Vth + rowB, g_Vtl + rowB, SEQ, SEQ,
              sbase, tid, acc);

    float* smf = reinterpret_cast<float*>(sm);
    acc_to_smem(acc, smf, tid);
    __syncthreads();

    const int row = tid >> 2, ch = (tid & 3) * 32;
    const size_t base = ((size_t)(b * SEQ + m0 + row)) * H + n0 + ch;
    float4* dst = reinterpret_cast<float4*>(out + base);
#pragma unroll
    for (int j4 = 0; j4 < 8; j4++)
        dst[j4] = *reinterpret_cast<const float4*>(&smf[row * SF + ch + j4 * 4]);
}

// ---------------------------------------------------------------------------
extern "C" void kernel_launch(void* const* d_in, const int* in_sizes, int n_in,
                              void* d_out, int out_size) {
    const float* x   = (const float*)d_in[0];
    const int*  mask = (const int*)  d_in[1];
    const float* Wq  = (const float*)d_in[2];
    const float* bq  = (const float*)d_in[3];
    const float* Wk  = (const float*)d_in[4];
    const float* bk  = (const float*)d_in[5];
    const float* Wv  = (const float*)d_in[6];
    const float* bv  = (const float*)d_in[7];
    float* out = (float*)d_out;

    cudaFuncSetAttribute(qkv_kernel,    cudaFuncAttributeMaxDynamicSharedMemorySize, SMEM_BYTES);
    cudaFuncSetAttribute(scores_kernel, cudaFuncAttributeMaxDynamicSharedMemorySize, SMEM_BYTES);
    cudaFuncSetAttribute(pv_kernel,     cudaFuncAttributeMaxDynamicSharedMemorySize, SMEM_BYTES);

    __nv_bfloat16 *Xh, *Xl, *Wh, *Wl;
    cudaGetSymbolAddress((void**)&Xh, g_Xh);
    cudaGetSymbolAddress((void**)&Xl, g_Xl);
    cudaGetSymbolAddress((void**)&Wh, g_Wh);
    cudaGetSymbolAddress((void**)&Wl, g_Wl);

    const int n4x = M_ALL * H / 4;
    const int n4w = H * H / 4;
    split_kernel<<<n4x / 256, 256>>>(x, Xh, Xl, n4x);
    split_kernel<<<n4w / 256, 256>>>(Wq, Wh + 0 * (size_t)H * H, Wl + 0 * (size_t)H * H, n4w);
    split_kernel<<<n4w / 256, 256>>>(Wk, Wh + 1 * (size_t)H * H, Wl + 1 * (size_t)H * H, n4w);
    split_kernel<<<n4w / 256, 256>>>(Wv, Wh + 2 * (size_t)H * H, Wl + 2 * (size_t)H * H, n4w);

    qkv_kernel   <<<dim3(H / 128, M_ALL / 128, 3), 512, SMEM_BYTES>>>(bq, bk, bv);
    scores_kernel<<<dim3(SEQ / 128, SEQ / 128, BATCH), 512, SMEM_BYTES>>>(mask);
    softmax_kernel<<<BATCH * SEQ, 256>>>();
    pv_kernel    <<<dim3(H / 128, SEQ / 128, BATCH), 512, SMEM_BYTES>>>(out);
}

// round 15
// speedup vs baseline: 1.0857x; 1.0857x over previous
#include <cuda_runtime.h>
#include <cuda_bf16.h>
#include <cstdint>
#include <math.h>

#define H       1024
#define BATCH   4
#define SEQ     2048
#define M_ALL   (BATCH * SEQ)

// ---------------------------------------------------------------------------
// Tiling: CTA 128x64, K-chunk 32, 8 warps (4 rows x 2 cols), warp tile 32x32.
// 3-stage cp.async pipeline, one __syncthreads per chunk, 2 CTAs/SM.
// ---------------------------------------------------------------------------
constexpr int RB          = 80;                 // smem bytes/row (64B data + 16B pad)
constexpr int TA_BYTES    = 128 * RB;           // 10240 (A tile: 128 rows)
constexpr int TB_BYTES    = 64 * RB;            // 5120  (B tile: 64 rows)
constexpr int OFF_AH      = 0;
constexpr int OFF_AL      = TA_BYTES;           // 10240
constexpr int OFF_BH      = 2 * TA_BYTES;       // 20480
constexpr int OFF_BL      = 2 * TA_BYTES + TB_BYTES;  // 25600
constexpr int STAGE_BYTES = 2 * TA_BYTES + 2 * TB_BYTES;  // 30720
constexpr int NSTAGE      = 3;
constexpr int SMEM_BYTES  = NSTAGE * STAGE_BYTES;  // 92160 -> 2 CTAs/SM
constexpr int SF          = 68;                 // epilogue f32 row stride (64+4)

// ---------------------------------------------------------------------------
// PTX helpers (sm_103 baseline ISA only: ldmatrix / mma.sync / cp.async)
// ---------------------------------------------------------------------------
__device__ __forceinline__ uint32_t smem_to_u32(const void* p) {
    uint32_t a;
    asm("{ .reg .u64 t; cvta.to.shared.u64 t, %1; cvt.u32.u64 %0, t; }" : "=r"(a) : "l"(p));
    return a;
}

#define CP_ASYNC16(dst, src) \
    asm volatile("cp.async.cg.shared.global [%0], [%1], 16;" :: "r"(dst), "l"(src))
#define CP_COMMIT() asm volatile("cp.async.commit_group;" ::: "memory")
#define CP_WAIT(n)  asm volatile("cp.async.wait_group %0;" :: "n"(n) : "memory")

#define LDSM_X4(r0, r1, r2, r3, addr) \
    asm volatile("ldmatrix.sync.aligned.m8n8.x4.shared.b16 {%0,%1,%2,%3}, [%4];" \
        : "=r"(r0), "=r"(r1), "=r"(r2), "=r"(r3) : "r"(addr))

__device__ __forceinline__ void mma16816(float* c, const uint32_t* a,
                                         uint32_t b0, uint32_t b1) {
    asm volatile(
        "mma.sync.aligned.m16n8k16.row.col.f32.bf16.bf16.f32 "
        "{%0,%1,%2,%3}, {%4,%5,%6,%7}, {%8,%9}, {%0,%1,%2,%3};"
        : "+f"(c[0]), "+f"(c[1]), "+f"(c[2]), "+f"(c[3])
        : "r"(a[0]), "r"(a[1]), "r"(a[2]), "r"(a[3]), "r"(b0), "r"(b1));
}

// ---------------------------------------------------------------------------
// Scratch (device globals; allocation-free)
// ---------------------------------------------------------------------------
__device__ __align__(256) __nv_bfloat16 g_Xh[(size_t)M_ALL * H];
__device__ __align__(256) __nv_bfloat16 g_Xl[(size_t)M_ALL * H];
__device__ __align__(256) __nv_bfloat16 g_Wh[3 * (size_t)H * H];
__device__ __align__(256) __nv_bfloat16 g_Wl[3 * (size_t)H * H];
__device__ __align__(256) __nv_bfloat16 g_Qh[(size_t)M_ALL * H];
__device__ __align__(256) __nv_bfloat16 g_Ql[(size_t)M_ALL * H];
__device__ __align__(256) __nv_bfloat16 g_Kh[(size_t)M_ALL * H];
__device__ __align__(256) __nv_bfloat16 g_Kl[(size_t)M_ALL * H];
__device__ __align__(256) __nv_bfloat16 g_Vth[(size_t)BATCH * H * SEQ];  // [b][h][s]
__device__ __align__(256) __nv_bfloat16 g_Vtl[(size_t)BATCH * H * SEQ];
__device__ __align__(256) float         g_S [(size_t)BATCH * SEQ * SEQ];
__device__ __align__(256) __nv_bfloat16 g_Ph[(size_t)BATCH * SEQ * SEQ];
__device__ __align__(256) __nv_bfloat16 g_Pl[(size_t)BATCH * SEQ * SEQ];

// ---------------------------------------------------------------------------
// Stage loaders (256 threads).  A tile: 128 rows x 32 bf16 -> 2 copies/thread.
// B tile: 64 rows -> 1 copy/thread.
// ---------------------------------------------------------------------------
__device__ __forceinline__ void stage_A(const __nv_bfloat16* __restrict__ g,
                                        size_t ld, int k0, uint32_t dst, int tid) {
#pragma unroll
    for (int i = 0; i < 2; i++) {
        int u = i * 256 + tid;      // 0..511
        int row = u >> 2, c = u & 3;
        CP_ASYNC16(dst + row * RB + c * 16, g + (size_t)row * ld + k0 + c * 8);
    }
}
__device__ __forceinline__ void stage_B(const __nv_bfloat16* __restrict__ g,
                                        size_t ld, int k0, uint32_t dst, int tid) {
    const int row = tid >> 2, c = tid & 3;  // 64 rows x 4
    CP_ASYNC16(dst + row * RB + c * 16, g + (size_t)row * ld + k0 + c * 8);
}

__device__ __forceinline__ void stage_all(const __nv_bfloat16* Ah, const __nv_bfloat16* Al,
                                          size_t lda,
                                          const __nv_bfloat16* Bh, const __nv_bfloat16* Bl,
                                          size_t ldb, int k0, uint32_t sb, int tid) {
    stage_A(Ah, lda, k0, sb + OFF_AH, tid);
    stage_A(Al, lda, k0, sb + OFF_AL, tid);
    stage_B(Bh, ldb, k0, sb + OFF_BH, tid);
    stage_B(Bl, ldb, k0, sb + OFF_BL, tid);
    CP_COMMIT();
}

// ---------------------------------------------------------------------------
// Compute one 32-wide K-chunk: 2 k16 steps x 3 products, warp tile 32x32
// ---------------------------------------------------------------------------
__device__ __forceinline__ void compute_stage(uint32_t st_base, uint32_t aByte,
                                              uint32_t bByte, float (&acc)[2][4][4]) {
#pragma unroll
    for (int ks = 0; ks < 2; ks++) {
        uint32_t ah[2][4], al[2][4], bh[2][4], bl[2][4];
#pragma unroll
        for (int np = 0; np < 2; np++) {
            uint32_t bo = st_base + bByte + np * 16 * RB + ks * 32;
            LDSM_X4(bh[np][0], bh[np][1], bh[np][2], bh[np][3], bo + OFF_BH);
            LDSM_X4(bl[np][0], bl[np][1], bl[np][2], bl[np][3], bo + OFF_BL);
        }
#pragma unroll
        for (int mt = 0; mt < 2; mt++) {
            uint32_t ao = st_base + aByte + mt * 16 * RB + ks * 32;
            LDSM_X4(ah[mt][0], ah[mt][1], ah[mt][2], ah[mt][3], ao + OFF_AH);
            LDSM_X4(al[mt][0], al[mt][1], al[mt][2], al[mt][3], ao + OFF_AL);
        }
#pragma unroll
        for (int mt = 0; mt < 2; mt++)
#pragma unroll
            for (int nt = 0; nt < 4; nt++) {
                const uint32_t b0h = bh[nt >> 1][(nt & 1) * 2];
                const uint32_t b1h = bh[nt >> 1][(nt & 1) * 2 + 1];
                const uint32_t b0l = bl[nt >> 1][(nt & 1) * 2];
                const uint32_t b1l = bl[nt >> 1][(nt & 1) * 2 + 1];
                mma16816(acc[mt][nt], ah[mt], b0h, b1h);
                mma16816(acc[mt][nt], ah[mt], b0l, b1l);
                mma16816(acc[mt][nt], al[mt], b0h, b1h);
            }
    }
}

// ---------------------------------------------------------------------------
// Full mainloop: D(128x64 f32, regs) = AhBh + AhBl + AlBh over Kdim.
// 3-stage pipeline, prefetch distance 2, ONE __syncthreads per chunk.
// ---------------------------------------------------------------------------
__device__ __forceinline__ void gemm_core(const __nv_bfloat16* Ah, const __nv_bfloat16* Al,
                                          size_t lda,
                                          const __nv_bfloat16* Bh, const __nv_bfloat16* Bl,
                                          size_t ldb, int Kdim, uint32_t sbase, int tid,
                                          float (&acc)[2][4][4]) {
    const int lane = tid & 31, wid = tid >> 5;
    const int wr = wid >> 1, wc = wid & 1;   // 4x2 warp grid
    const uint32_t aByte = sbase + (uint32_t)((wr * 32 + (lane & 15)) * RB + (lane >> 4) * 16);
    const uint32_t bByte = sbase + (uint32_t)((wc * 32 + (lane & 7) + ((lane >> 4) & 1) * 8) * RB
                                              + ((lane >> 3) & 1) * 16);

    const int nch = Kdim / 32;
    stage_all(Ah, Al, lda, Bh, Bl, ldb, 0,  sbase + 0 * STAGE_BYTES, tid);
    stage_all(Ah, Al, lda, Bh, Bl, ldb, 32, sbase + 1 * STAGE_BYTES, tid);

    int ld_stage = 2;
    int cm_stage = 0;
#pragma unroll 1
    for (int c = 0; c < nch; c++) {
        CP_WAIT(1);
        __syncthreads();
        if (c + 2 < nch) {
            stage_all(Ah, Al, lda, Bh, Bl, ldb, (c + 2) * 32,
                      sbase + (uint32_t)(ld_stage * STAGE_BYTES), tid);
        } else {
            CP_COMMIT();   // empty group keeps wait_group arithmetic exact
        }
        ld_stage = (ld_stage == NSTAGE - 1) ? 0 : ld_stage + 1;
        compute_stage((uint32_t)(cm_stage * STAGE_BYTES), aByte, bByte, acc);
        cm_stage = (cm_stage == NSTAGE - 1) ? 0 : cm_stage + 1;
    }
    CP_WAIT(0);
    __syncthreads();
}

// Scatter warp accumulators into a 128x64 f32 smem tile (stride SF)
__device__ __forceinline__ void acc_to_smem(float (&acc)[2][4][4], float* smf, int tid) {
    const int lane = tid & 31, wid = tid >> 5;
    const int wr = wid >> 1, wc = wid & 1;
    const int g = lane >> 2, t = lane & 3;
#pragma unroll
    for (int mt = 0; mt < 2; mt++)
#pragma unroll
        for (int nt = 0; nt < 4; nt++) {
            const int m = wr * 32 + mt * 16 + g;
            const int n = wc * 32 + nt * 8 + 2 * t;
            *reinterpret_cast<float2*>(&smf[m * SF + n]) =
                make_float2(acc[mt][nt][0], acc[mt][nt][1]);
            *reinterpret_cast<float2*>(&smf[(m + 8) * SF + n]) =
                make_float2(acc[mt][nt][2], acc[mt][nt][3]);
        }
}

// ---------------------------------------------------------------------------
// Kernel: fp32 -> (hi, lo) bf16 split
// ---------------------------------------------------------------------------
__global__ void split_kernel(const float* __restrict__ src,
                             __nv_bfloat16* __restrict__ dh,
                             __nv_bfloat16* __restrict__ dl, int n4) {
    int i = blockIdx.x * blockDim.x + threadIdx.x;
    if (i >= n4) return;
    float4 v = reinterpret_cast<const float4*>(src)[i];
    float vv[4] = {v.x, v.y, v.z, v.w};
    __nv_bfloat16 hh[4], ll[4];
#pragma unroll
    for (int j = 0; j < 4; j++) {
        hh[j] = __float2bfloat16(vv[j]);
        ll[j] = __float2bfloat16(vv[j] - __bfloat162float(hh[j]));
    }
    reinterpret_cast<__nv_bfloat162*>(dh)[2 * i]     = __halves2bfloat162(hh[0], hh[1]);
    reinterpret_cast<__nv_bfloat162*>(dh)[2 * i + 1] = __halves2bfloat162(hh[2], hh[3]);
    reinterpret_cast<__nv_bfloat162*>(dl)[2 * i]     = __halves2bfloat162(ll[0], ll[1]);
    reinterpret_cast<__nv_bfloat162*>(dl)[2 * i + 1] = __halves2bfloat162(ll[2], ll[3]);
}

// ---------------------------------------------------------------------------
// Kernel 1: QKV projection.  z=0 -> Q (split), z=1 -> K (split), z=2 -> V^T
// grid = (H/64, M_ALL/128, 3), block = 256
// ---------------------------------------------------------------------------
__global__ void __launch_bounds__(256, 2)
qkv_kernel(const float* __restrict__ bq, const float* __restrict__ bk,
           const float* __restrict__ bv) {
    extern __shared__ char sm[];
    const uint32_t sbase = smem_to_u32(sm);
    const int tid = threadIdx.x;
    const int z = blockIdx.z;
    const int m0 = blockIdx.y * 128, n0 = blockIdx.x * 64;

    const __nv_bfloat16* Ah = g_Xh + (size_t)m0 * H;
    const __nv_bfloat16* Al = g_Xl + (size_t)m0 * H;
    const __nv_bfloat16* Bh = g_Wh + (size_t)z * H * H + (size_t)n0 * H;
    const __nv_bfloat16* Bl = g_Wl + (size_t)z * H * H + (size_t)n0 * H;
    const float* bias = (z == 0) ? bq : (z == 1) ? bk : bv;

    float acc[2][4][4] = {};
    gemm_core(Ah, Al, H, Bh, Bl, H, H, sbase, tid, acc);

    float* smf = reinterpret_cast<float*>(sm);
    acc_to_smem(acc, smf, tid);
    __syncthreads();

    if (z < 2) {
        __nv_bfloat16* outH = (z == 0) ? g_Qh : g_Kh;
        __nv_bfloat16* outL = (z == 0) ? g_Ql : g_Kl;
        const int row = tid >> 1, ch = (tid & 1) * 32;
        const size_t go = (size_t)(m0 + row) * H + n0 + ch;
#pragma unroll
        for (int q = 0; q < 4; q++) {
            uint32_t ph[4], pl[4];
#pragma unroll
            for (int j = 0; j < 4; j++) {
                const int n = ch + q * 8 + 2 * j;
                float c0 = smf[row * SF + n]     + bias[n0 + n];
                float c1 = smf[row * SF + n + 1] + bias[n0 + n + 1];
                __nv_bfloat16 h0 = __float2bfloat16(c0), h1 = __float2bfloat16(c1);
                __nv_bfloat16 l0 = __float2bfloat16(c0 - __bfloat162float(h0));
                __nv_bfloat16 l1 = __float2bfloat16(c1 - __bfloat162float(h1));
                __nv_bfloat162 vh = __halves2bfloat162(h0, h1);
                __nv_bfloat162 vl = __halves2bfloat162(l0, l1);
                ph[j] = *reinterpret_cast<uint32_t*>(&vh);
                pl[j] = *reinterpret_cast<uint32_t*>(&vl);
            }
            *reinterpret_cast<uint4*>(outH + go + q * 8) = *reinterpret_cast<const uint4*>(ph);
            *reinterpret_cast<uint4*>(outL + go + q * 8) = *reinterpret_cast<const uint4*>(pl);
        }
    } else {
        // V transposed: Vt[b][n][s]; threads map to s -> coalesced stores
        const int b = m0 >> 11;
        const int s0 = m0 & 2047;
        const int sl = tid & 127, nh = (tid >> 7) * 32;
#pragma unroll 1
        for (int j = 0; j < 32; j++) {
            const int nl = nh + j;
            float c = smf[sl * SF + nl] + bias[n0 + nl];
            __nv_bfloat16 hv = __float2bfloat16(c);
            __nv_bfloat16 lv = __float2bfloat16(c - __bfloat162float(hv));
            const size_t a = (size_t)b * H * SEQ + (size_t)(n0 + nl) * SEQ + s0 + sl;
            g_Vth[a] = hv;
            g_Vtl[a] = lv;
        }
    }
}

// ---------------------------------------------------------------------------
// Kernel 2: scores S = mask ? (Q.K^T)/32 : -inf.  grid = (32, 16, 4), block 256
// ---------------------------------------------------------------------------
__global__ void __launch_bounds__(256, 2)
scores_kernel(const int* __restrict__ mask) {
    extern __shared__ char sm[];
    const uint32_t sbase = smem_to_u32(sm);
    const int tid = threadIdx.x;
    const int b = blockIdx.z;
    const int m0 = blockIdx.y * 128, n0 = blockIdx.x * 64;

    const size_t rowA = (size_t)(b * SEQ + m0) * H;
    const size_t rowB = (size_t)(b * SEQ + n0) * H;

    float acc[2][4][4] = {};
    gemm_core(g_Qh + rowA, g_Ql + rowA, H, g_Kh + rowB, g_Kl + rowB, H, H,
              sbase, tid, acc);

    float* smf = reinterpret_cast<float*>(sm);
    acc_to_smem(acc, smf, tid);
    __syncthreads();

    const float scale = 0.03125f;  // 1/sqrt(1024)
    const int ql = tid >> 1, ch = (tid & 1) * 32;
    const size_t base = ((size_t)(b * SEQ + m0 + ql)) * SEQ + n0 + ch;
    const int4* mk4 = reinterpret_cast<const int4*>(mask + base);
    float4* dst = reinterpret_cast<float4*>(g_S + base);
#pragma unroll
    for (int j4 = 0; j4 < 8; j4++) {
        float4 v = *reinterpret_cast<const float4*>(&smf[ql * SF + ch + j4 * 4]);
        int4 mk = mk4[j4];
        v.x = mk.x ? v.x * scale : -INFINITY;
        v.y = mk.y ? v.y * scale : -INFINITY;
        v.z = mk.z ? v.z * scale : -INFINITY;
        v.w = mk.w ? v.w * scale : -INFINITY;
        dst[j4] = v;
    }
}

// ---------------------------------------------------------------------------
// Kernel 3: row softmax, fp32 in -> split-bf16 P out.  grid = B*S, block 256
// ---------------------------------------------------------------------------
__global__ void softmax_kernel() {
    const size_t row = (size_t)blockIdx.x * SEQ;
    const float* Srow = g_S + row;
    const int tid = threadIdx.x;

    float v[8];
    float m = -INFINITY;
#pragma unroll
    for (int i = 0; i < 8; i++) {
        v[i] = Srow[i * 256 + tid];
        m = fmaxf(m, v[i]);
    }
#pragma unroll
    for (int o = 16; o > 0; o >>= 1) m = fmaxf(m, __shfl_xor_sync(0xffffffffu, m, o));
    __shared__ float smax[8];
    if ((tid & 31) == 0) smax[tid >> 5] = m;
    __syncthreads();
    float mm = smax[0];
#pragma unroll
    for (int i = 1; i < 8; i++) mm = fmaxf(mm, smax[i]);

    float s = 0.f;
#pragma unroll
    for (int i = 0; i < 8; i++) { v[i] = __expf(v[i] - mm); s += v[i]; }
#pragma unroll
    for (int o = 16; o > 0; o >>= 1) s += __shfl_xor_sync(0xffffffffu, s, o);
    __shared__ float ssum[8];
    if ((tid & 31) == 0) ssum[tid >> 5] = s;
    __syncthreads();
    float tot = 0.f;
#pragma unroll
    for (int i = 0; i < 8; i++) tot += ssum[i];
    const float inv = 1.0f / tot;
#pragma unroll
    for (int i = 0; i < 8; i++) {
        float p = v[i] * inv;
        __nv_bfloat16 h = __float2bfloat16(p);
        __nv_bfloat16 l = __float2bfloat16(p - __bfloat162float(h));
        g_Ph[row + i * 256 + tid] = h;
        g_Pl[row + i * 256 + tid] = l;
    }
}

// ---------------------------------------------------------------------------
// Kernel 4: out = P @ V (NT vs V^T).  grid = (H/64, SEQ/128, 4), block 256
// ---------------------------------------------------------------------------
__global__ void __launch_bounds__(256, 2)
pv_kernel(float* __restrict__ out) {
    extern __shared__ char sm[];
    const uint32_t sbase = smem_to_u32(sm);
    const int tid = threadIdx.x;
    const int b = blockIdx.z;
    const int m0 = blockIdx.y * 128, n0 = blockIdx.x * 64;

    const size_t rowA = ((size_t)b * SEQ + m0) * SEQ;
    const size_t rowB = (size_t)b * H * SEQ + (size_t)n0 * SEQ;

    float acc[2][4][4] = {};
    gemm_core(g_Ph + rowA, g_Pl + rowA, SEQ, g_Vth + rowB, g_Vtl + rowB, SEQ, SEQ,
              sbase, tid, acc);

    float* smf = reinterpret_cast<float*>(sm);
    acc_to_smem(acc, smf, tid);
    __syncthreads();

    const int row = tid >> 1, ch = (tid & 1) * 32;
    const size_t base = ((size_t)(b * SEQ + m0 + row)) * H + n0 + ch;
    float4* dst = reinterpret_cast<float4*>(out + base);
#pragma unroll
    for (int j4 = 0; j4 < 8; j4++)
        dst[j4] = *reinterpret_cast<const float4*>(&smf[row * SF + ch + j4 * 4]);
}

// ---------------------------------------------------------------------------
extern "C" void kernel_launch(void* const* d_in, const int* in_sizes, int n_in,
                              void* d_out, int out_size) {
    const float* x   = (const float*)d_in[0];
    const int*  mask = (const int*)  d_in[1];
    const float* Wq  = (const float*)d_in[2];
    const float* bq  = (const float*)d_in[3];
    const float* Wk  = (const float*)d_in[4];
    const float* bk  = (const float*)d_in[5];
    const float* Wv  = (const float*)d_in[6];
    const float* bv  = (const float*)d_in[7];
    float* out = (float*)d_out;

    cudaFuncSetAttribute(qkv_kernel,    cudaFuncAttributeMaxDynamicSharedMemorySize, SMEM_BYTES);
    cudaFuncSetAttribute(scores_kernel, cudaFuncAttributeMaxDynamicSharedMemorySize, SMEM_BYTES);
    cudaFuncSetAttribute(pv_kernel,     cudaFuncAttributeMaxDynamicSharedMemorySize, SMEM_BYTES);

    __nv_bfloat16 *Xh, *Xl, *Wh, *Wl;
    cudaGetSymbolAddress((void**)&Xh, g_Xh);
    cudaGetSymbolAddress((void**)&Xl, g_Xl);
    cudaGetSymbolAddress((void**)&Wh, g_Wh);
    cudaGetSymbolAddress((void**)&Wl, g_Wl);

    const int n4x = M_ALL * H / 4;
    const int n4w = H * H / 4;
    split_kernel<<<n4x / 256, 256>>>(x, Xh, Xl, n4x);
    split_kernel<<<n4w / 256, 256>>>(Wq, Wh + 0 * (size_t)H * H, Wl + 0 * (size_t)H * H, n4w);
    split_kernel<<<n4w / 256, 256>>>(Wk, Wh + 1 * (size_t)H * H, Wl + 1 * (size_t)H * H, n4w);
    split_kernel<<<n4w / 256, 256>>>(Wv, Wh + 2 * (size_t)H * H, Wl + 2 * (size_t)H * H, n4w);

    qkv_kernel   <<<dim3(H / 64, M_ALL / 128, 3), 256, SMEM_BYTES>>>(bq, bk, bv);
    scores_kernel<<<dim3(SEQ / 64, SEQ / 128, BATCH), 256, SMEM_BYTES>>>(mask);
    softmax_kernel<<<BATCH * SEQ, 256>>>();
    pv_kernel    <<<dim3(H / 64, SEQ / 128, BATCH), 256, SMEM_BYTES>>>(out);
}

// round 16
// speedup vs baseline: 1.2823x; 1.1812x over previous
#include <cuda_runtime.h>
#include <cuda_bf16.h>
#include <cuda_fp16.h>
#include <cstdint>
#include <math.h>

#define H       1024
#define BATCH   4
#define SEQ     2048
#define M_ALL   (BATCH * SEQ)

// ---------------------------------------------------------------------------
// Tiling: CTA 128x64, K-chunk 32, 8 warps (4 rows x 2 cols), warp tile 32x32.
// QKV/scores: bf16x3 split (3 products). PV: fp16 single product.
// 3-stage cp.async pipeline, one __syncthreads per chunk, 2 CTAs/SM.
// ---------------------------------------------------------------------------
constexpr int RB          = 80;                 // smem bytes/row (64B data + 16B pad)
constexpr int TA_BYTES    = 128 * RB;           // 10240 (A tile: 128 rows)
constexpr int TB_BYTES    = 64 * RB;            // 5120  (B tile: 64 rows)
constexpr int OFF_AH      = 0;
constexpr int OFF_AL      = TA_BYTES;
constexpr int OFF_BH      = 2 * TA_BYTES;
constexpr int OFF_BL      = 2 * TA_BYTES + TB_BYTES;
constexpr int STAGE_BYTES = 2 * TA_BYTES + 2 * TB_BYTES;   // 30720
constexpr int NSTAGE      = 3;
constexpr int SMEM_BYTES  = NSTAGE * STAGE_BYTES;          // 92160 -> 2 CTAs/SM
// PV single-product layout
constexpr int P_OFF_A       = 0;
constexpr int P_OFF_B       = TA_BYTES;
constexpr int P_STAGE_BYTES = TA_BYTES + TB_BYTES;         // 15360
constexpr int PV_SMEM_BYTES = NSTAGE * P_STAGE_BYTES;      // 46080 (epi needs 34816)
constexpr int SF          = 68;                 // epilogue f32 row stride (64+4)

// ---------------------------------------------------------------------------
// PTX helpers (sm_103 baseline ISA only: ldmatrix / mma.sync / cp.async)
// ---------------------------------------------------------------------------
__device__ __forceinline__ uint32_t smem_to_u32(const void* p) {
    uint32_t a;
    asm("{ .reg .u64 t; cvta.to.shared.u64 t, %1; cvt.u32.u64 %0, t; }" : "=r"(a) : "l"(p));
    return a;
}

#define CP_ASYNC16(dst, src) \
    asm volatile("cp.async.cg.shared.global [%0], [%1], 16;" :: "r"(dst), "l"(src))
#define CP_COMMIT() asm volatile("cp.async.commit_group;" ::: "memory")
#define CP_WAIT(n)  asm volatile("cp.async.wait_group %0;" :: "n"(n) : "memory")

#define LDSM_X4(r0, r1, r2, r3, addr) \
    asm volatile("ldmatrix.sync.aligned.m8n8.x4.shared.b16 {%0,%1,%2,%3}, [%4];" \
        : "=r"(r0), "=r"(r1), "=r"(r2), "=r"(r3) : "r"(addr))

__device__ __forceinline__ void mma16816(float* c, const uint32_t* a,
                                         uint32_t b0, uint32_t b1) {
    asm volatile(
        "mma.sync.aligned.m16n8k16.row.col.f32.bf16.bf16.f32 "
        "{%0,%1,%2,%3}, {%4,%5,%6,%7}, {%8,%9}, {%0,%1,%2,%3};"
        : "+f"(c[0]), "+f"(c[1]), "+f"(c[2]), "+f"(c[3])
        : "r"(a[0]), "r"(a[1]), "r"(a[2]), "r"(a[3]), "r"(b0), "r"(b1));
}
__device__ __forceinline__ void mma16816h(float* c, const uint32_t* a,
                                          uint32_t b0, uint32_t b1) {
    asm volatile(
        "mma.sync.aligned.m16n8k16.row.col.f32.f16.f16.f32 "
        "{%0,%1,%2,%3}, {%4,%5,%6,%7}, {%8,%9}, {%0,%1,%2,%3};"
        : "+f"(c[0]), "+f"(c[1]), "+f"(c[2]), "+f"(c[3])
        : "r"(a[0]), "r"(a[1]), "r"(a[2]), "r"(a[3]), "r"(b0), "r"(b1));
}

// ---------------------------------------------------------------------------
// Scratch (device globals; allocation-free)
// ---------------------------------------------------------------------------
__device__ __align__(256) __nv_bfloat16 g_Xh[(size_t)M_ALL * H];
__device__ __align__(256) __nv_bfloat16 g_Xl[(size_t)M_ALL * H];
__device__ __align__(256) __nv_bfloat16 g_Wh[3 * (size_t)H * H];
__device__ __align__(256) __nv_bfloat16 g_Wl[3 * (size_t)H * H];
__device__ __align__(256) __nv_bfloat16 g_Qh[(size_t)M_ALL * H];
__device__ __align__(256) __nv_bfloat16 g_Ql[(size_t)M_ALL * H];
__device__ __align__(256) __nv_bfloat16 g_Kh[(size_t)M_ALL * H];
__device__ __align__(256) __nv_bfloat16 g_Kl[(size_t)M_ALL * H];
__device__ __align__(256) __half        g_Vtf[(size_t)BATCH * H * SEQ];  // [b][h][s], fp16
__device__ __align__(256) float         g_S [(size_t)BATCH * SEQ * SEQ];
__device__ __align__(256) __half        g_Pf[(size_t)BATCH * SEQ * SEQ]; // fp16

// ---------------------------------------------------------------------------
// Stage loaders (256 threads).  A tile: 128 rows x 32 elems -> 2 copies/thread.
// B tile: 64 rows -> 1 copy/thread.  T = bf16 or half (2B elems).
// ---------------------------------------------------------------------------
template <typename T>
__device__ __forceinline__ void stage_A(const T* __restrict__ g,
                                        size_t ld, int k0, uint32_t dst, int tid) {
#pragma unroll
    for (int i = 0; i < 2; i++) {
        int u = i * 256 + tid;
        int row = u >> 2, c = u & 3;
        CP_ASYNC16(dst + row * RB + c * 16, g + (size_t)row * ld + k0 + c * 8);
    }
}
template <typename T>
__device__ __forceinline__ void stage_B(const T* __restrict__ g,
                                        size_t ld, int k0, uint32_t dst, int tid) {
    const int row = tid >> 2, c = tid & 3;
    CP_ASYNC16(dst + row * RB + c * 16, g + (size_t)row * ld + k0 + c * 8);
}

__device__ __forceinline__ void stage_all(const __nv_bfloat16* Ah, const __nv_bfloat16* Al,
                                          size_t lda,
                                          const __nv_bfloat16* Bh, const __nv_bfloat16* Bl,
                                          size_t ldb, int k0, uint32_t sb, int tid) {
    stage_A(Ah, lda, k0, sb + OFF_AH, tid);
    stage_A(Al, lda, k0, sb + OFF_AL, tid);
    stage_B(Bh, ldb, k0, sb + OFF_BH, tid);
    stage_B(Bl, ldb, k0, sb + OFF_BL, tid);
    CP_COMMIT();
}
__device__ __forceinline__ void stage_all_1p(const __half* A, size_t lda,
                                             const __half* B, size_t ldb,
                                             int k0, uint32_t sb, int tid) {
    stage_A(A, lda, k0, sb + P_OFF_A, tid);
    stage_B(B, ldb, k0, sb + P_OFF_B, tid);
    CP_COMMIT();
}

// ---------------------------------------------------------------------------
// Compute one 32-wide K-chunk: bf16x3 (2 k16 steps x 3 products)
// ---------------------------------------------------------------------------
__device__ __forceinline__ void compute_stage(uint32_t st_base, uint32_t aByte,
                                              uint32_t bByte, float (&acc)[2][4][4]) {
#pragma unroll
    for (int ks = 0; ks < 2; ks++) {
        uint32_t ah[2][4], al[2][4], bh[2][4], bl[2][4];
#pragma unroll
        for (int np = 0; np < 2; np++) {
            uint32_t bo = st_base + bByte + np * 16 * RB + ks * 32;
            LDSM_X4(bh[np][0], bh[np][1], bh[np][2], bh[np][3], bo + OFF_BH);
            LDSM_X4(bl[np][0], bl[np][1], bl[np][2], bl[np][3], bo + OFF_BL);
        }
#pragma unroll
        for (int mt = 0; mt < 2; mt++) {
            uint32_t ao = st_base + aByte + mt * 16 * RB + ks * 32;
            LDSM_X4(ah[mt][0], ah[mt][1], ah[mt][2], ah[mt][3], ao + OFF_AH);
            LDSM_X4(al[mt][0], al[mt][1], al[mt][2], al[mt][3], ao + OFF_AL);
        }
#pragma unroll
        for (int mt = 0; mt < 2; mt++)
#pragma unroll
            for (int nt = 0; nt < 4; nt++) {
                const uint32_t b0h = bh[nt >> 1][(nt & 1) * 2];
                const uint32_t b1h = bh[nt >> 1][(nt & 1) * 2 + 1];
                const uint32_t b0l = bl[nt >> 1][(nt & 1) * 2];
                const uint32_t b1l = bl[nt >> 1][(nt & 1) * 2 + 1];
                mma16816(acc[mt][nt], ah[mt], b0h, b1h);
                mma16816(acc[mt][nt], ah[mt], b0l, b1l);
                mma16816(acc[mt][nt], al[mt], b0h, b1h);
            }
    }
}
// fp16 single product
__device__ __forceinline__ void compute_stage_1p(uint32_t st_base, uint32_t aByte,
                                                 uint32_t bByte, float (&acc)[2][4][4]) {
#pragma unroll
    for (int ks = 0; ks < 2; ks++) {
        uint32_t ah[2][4], bh[2][4];
#pragma unroll
        for (int np = 0; np < 2; np++) {
            uint32_t bo = st_base + bByte + np * 16 * RB + ks * 32;
            LDSM_X4(bh[np][0], bh[np][1], bh[np][2], bh[np][3], bo + P_OFF_B);
        }
#pragma unroll
        for (int mt = 0; mt < 2; mt++) {
            uint32_t ao = st_base + aByte + mt * 16 * RB + ks * 32;
            LDSM_X4(ah[mt][0], ah[mt][1], ah[mt][2], ah[mt][3], ao + P_OFF_A);
        }
#pragma unroll
        for (int mt = 0; mt < 2; mt++)
#pragma unroll
            for (int nt = 0; nt < 4; nt++) {
                const uint32_t b0 = bh[nt >> 1][(nt & 1) * 2];
                const uint32_t b1 = bh[nt >> 1][(nt & 1) * 2 + 1];
                mma16816h(acc[mt][nt], ah[mt], b0, b1);
            }
    }
}

// Per-lane ldmatrix base offsets (shared by both cores)
__device__ __forceinline__ uint32_t a_byte_off(uint32_t sbase, int wid, int lane) {
    const int wr = wid >> 1;
    return sbase + (uint32_t)((wr * 32 + (lane & 15)) * RB + (lane >> 4) * 16);
}
__device__ __forceinline__ uint32_t b_byte_off(uint32_t sbase, int wid, int lane) {
    const int wc = wid & 1;
    return sbase + (uint32_t)((wc * 32 + (lane & 7) + ((lane >> 4) & 1) * 8) * RB
                              + ((lane >> 3) & 1) * 16);
}

// ---------------------------------------------------------------------------
// Mainloops: 3-stage pipeline, prefetch distance 2, ONE __syncthreads/chunk.
// ---------------------------------------------------------------------------
__device__ __forceinline__ void gemm_core(const __nv_bfloat16* Ah, const __nv_bfloat16* Al,
                                          size_t lda,
                                          const __nv_bfloat16* Bh, const __nv_bfloat16* Bl,
                                          size_t ldb, int Kdim, uint32_t sbase, int tid,
                                          float (&acc)[2][4][4]) {
    const int lane = tid & 31, wid = tid >> 5;
    const uint32_t aByte = a_byte_off(sbase, wid, lane);
    const uint32_t bByte = b_byte_off(sbase, wid, lane);

    const int nch = Kdim / 32;
    stage_all(Ah, Al, lda, Bh, Bl, ldb, 0,  sbase + 0 * STAGE_BYTES, tid);
    stage_all(Ah, Al, lda, Bh, Bl, ldb, 32, sbase + 1 * STAGE_BYTES, tid);

    int ld_stage = 2, cm_stage = 0;
#pragma unroll 1
    for (int c = 0; c < nch; c++) {
        CP_WAIT(1);
        __syncthreads();
        if (c + 2 < nch) {
            stage_all(Ah, Al, lda, Bh, Bl, ldb, (c + 2) * 32,
                      sbase + (uint32_t)(ld_stage * STAGE_BYTES), tid);
        } else {
            CP_COMMIT();
        }
        ld_stage = (ld_stage == NSTAGE - 1) ? 0 : ld_stage + 1;
        compute_stage((uint32_t)(cm_stage * STAGE_BYTES), aByte, bByte, acc);
        cm_stage = (cm_stage == NSTAGE - 1) ? 0 : cm_stage + 1;
    }
    CP_WAIT(0);
    __syncthreads();
}

__device__ __forceinline__ void gemm_core_1p(const __half* A, size_t lda,
                                             const __half* B, size_t ldb,
                                             int Kdim, uint32_t sbase, int tid,
                                             float (&acc)[2][4][4]) {
    const int lane = tid & 31, wid = tid >> 5;
    const uint32_t aByte = a_byte_off(sbase, wid, lane);
    const uint32_t bByte = b_byte_off(sbase, wid, lane);

    const int nch = Kdim / 32;
    stage_all_1p(A, lda, B, ldb, 0,  sbase + 0 * P_STAGE_BYTES, tid);
    stage_all_1p(A, lda, B, ldb, 32, sbase + 1 * P_STAGE_BYTES, tid);

    int ld_stage = 2, cm_stage = 0;
#pragma unroll 1
    for (int c = 0; c < nch; c++) {
        CP_WAIT(1);
        __syncthreads();
        if (c + 2 < nch) {
            stage_all_1p(A, lda, B, ldb, (c + 2) * 32,
                         sbase + (uint32_t)(ld_stage * P_STAGE_BYTES), tid);
        } else {
            CP_COMMIT();
        }
        ld_stage = (ld_stage == NSTAGE - 1) ? 0 : ld_stage + 1;
        compute_stage_1p((uint32_t)(cm_stage * P_STAGE_BYTES), aByte, bByte, acc);
        cm_stage = (cm_stage == NSTAGE - 1) ? 0 : cm_stage + 1;
    }
    CP_WAIT(0);
    __syncthreads();
}

// Scatter warp accumulators into a 128x64 f32 smem tile (stride SF)
__device__ __forceinline__ void acc_to_smem(float (&acc)[2][4][4], float* smf, int tid) {
    const int lane = tid & 31, wid = tid >> 5;
    const int wr = wid >> 1, wc = wid & 1;
    const int g = lane >> 2, t = lane & 3;
#pragma unroll
    for (int mt = 0; mt < 2; mt++)
#pragma unroll
        for (int nt = 0; nt < 4; nt++) {
            const int m = wr * 32 + mt * 16 + g;
            const int n = wc * 32 + nt * 8 + 2 * t;
            *reinterpret_cast<float2*>(&smf[m * SF + n]) =
                make_float2(acc[mt][nt][0], acc[mt][nt][1]);
            *reinterpret_cast<float2*>(&smf[(m + 8) * SF + n]) =
                make_float2(acc[mt][nt][2], acc[mt][nt][3]);
        }
}

// ---------------------------------------------------------------------------
// Kernel: fp32 -> (hi, lo) bf16 split
// ---------------------------------------------------------------------------
__global__ void split_kernel(const float* __restrict__ src,
                             __nv_bfloat16* __restrict__ dh,
                             __nv_bfloat16* __restrict__ dl, int n4) {
    int i = blockIdx.x * blockDim.x + threadIdx.x;
    if (i >= n4) return;
    float4 v = reinterpret_cast<const float4*>(src)[i];
    float vv[4] = {v.x, v.y, v.z, v.w};
    __nv_bfloat16 hh[4], ll[4];
#pragma unroll
    for (int j = 0; j < 4; j++) {
        hh[j] = __float2bfloat16(vv[j]);
        ll[j] = __float2bfloat16(vv[j] - __bfloat162float(hh[j]));
    }
    reinterpret_cast<__nv_bfloat162*>(dh)[2 * i]     = __halves2bfloat162(hh[0], hh[1]);
    reinterpret_cast<__nv_bfloat162*>(dh)[2 * i + 1] = __halves2bfloat162(hh[2], hh[3]);
    reinterpret_cast<__nv_bfloat162*>(dl)[2 * i]     = __halves2bfloat162(ll[0], ll[1]);
    reinterpret_cast<__nv_bfloat162*>(dl)[2 * i + 1] = __halves2bfloat162(ll[2], ll[3]);
}

// ---------------------------------------------------------------------------
// Kernel 1: QKV projection.  z=0 -> Q (split), z=1 -> K (split), z=2 -> V^T fp16
// grid = (H/64, M_ALL/128, 3), block = 256
// ---------------------------------------------------------------------------
__global__ void __launch_bounds__(256, 2)
qkv_kernel(const float* __restrict__ bq, const float* __restrict__ bk,
           const float* __restrict__ bv) {
    extern __shared__ char sm[];
    const uint32_t sbase = smem_to_u32(sm);
    const int tid = threadIdx.x;
    const int z = blockIdx.z;
    const int m0 = blockIdx.y * 128, n0 = blockIdx.x * 64;

    const __nv_bfloat16* Ah = g_Xh + (size_t)m0 * H;
    const __nv_bfloat16* Al = g_Xl + (size_t)m0 * H;
    const __nv_bfloat16* Bh = g_Wh + (size_t)z * H * H + (size_t)n0 * H;
    const __nv_bfloat16* Bl = g_Wl + (size_t)z * H * H + (size_t)n0 * H;
    const float* bias = (z == 0) ? bq : (z == 1) ? bk : bv;

    float acc[2][4][4] = {};
    gemm_core(Ah, Al, H, Bh, Bl, H, H, sbase, tid, acc);

    float* smf = reinterpret_cast<float*>(sm);
    acc_to_smem(acc, smf, tid);
    __syncthreads();

    if (z < 2) {
        __nv_bfloat16* outH = (z == 0) ? g_Qh : g_Kh;
        __nv_bfloat16* outL = (z == 0) ? g_Ql : g_Kl;
        const int row = tid >> 1, ch = (tid & 1) * 32;
        const size_t go = (size_t)(m0 + row) * H + n0 + ch;
#pragma unroll
        for (int q = 0; q < 4; q++) {
            uint32_t ph[4], pl[4];
#pragma unroll
            for (int j = 0; j < 4; j++) {
                const int n = ch + q * 8 + 2 * j;
                float c0 = smf[row * SF + n]     + bias[n0 + n];
                float c1 = smf[row * SF + n + 1] + bias[n0 + n + 1];
                __nv_bfloat16 h0 = __float2bfloat16(c0), h1 = __float2bfloat16(c1);
                __nv_bfloat16 l0 = __float2bfloat16(c0 - __bfloat162float(h0));
                __nv_bfloat16 l1 = __float2bfloat16(c1 - __bfloat162float(h1));
                __nv_bfloat162 vh = __halves2bfloat162(h0, h1);
                __nv_bfloat162 vl = __halves2bfloat162(l0, l1);
                ph[j] = *reinterpret_cast<uint32_t*>(&vh);
                pl[j] = *reinterpret_cast<uint32_t*>(&vl);
            }
            *reinterpret_cast<uint4*>(outH + go + q * 8) = *reinterpret_cast<const uint4*>(ph);
            *reinterpret_cast<uint4*>(outL + go + q * 8) = *reinterpret_cast<const uint4*>(pl);
        }
    } else {
        // V transposed fp16: Vt[b][n][s]; threads map to s -> coalesced stores
        const int b = m0 >> 11;
        const int s0 = m0 & 2047;
        const int sl = tid & 127, nh = (tid >> 7) * 32;
#pragma unroll 1
        for (int j = 0; j < 32; j++) {
            const int nl = nh + j;
            float c = smf[sl * SF + nl] + bias[n0 + nl];
            const size_t a = (size_t)b * H * SEQ + (size_t)(n0 + nl) * SEQ + s0 + sl;
            g_Vtf[a] = __float2half(c);
        }
    }
}

// ---------------------------------------------------------------------------
// Kernel 2: scores S = mask ? (Q.K^T)/32 : -inf.  grid = (32, 16, 4), block 256
// ---------------------------------------------------------------------------
__global__ void __launch_bounds__(256, 2)
scores_kernel(const int* __restrict__ mask) {
    extern __shared__ char sm[];
    const uint32_t sbase = smem_to_u32(sm);
    const int tid = threadIdx.x;
    const int b = blockIdx.z;
    const int m0 = blockIdx.y * 128, n0 = blockIdx.x * 64;

    const size_t rowA = (size_t)(b * SEQ + m0) * H;
    const size_t rowB = (size_t)(b * SEQ + n0) * H;

    float acc[2][4][4] = {};
    gemm_core(g_Qh + rowA, g_Ql + rowA, H, g_Kh + rowB, g_Kl + rowB, H, H,
              sbase, tid, acc);

    float* smf = reinterpret_cast<float*>(sm);
    acc_to_smem(acc, smf, tid);
    __syncthreads();

    const float scale = 0.03125f;  // 1/sqrt(1024)
    const int ql = tid >> 1, ch = (tid & 1) * 32;
    const size_t base = ((size_t)(b * SEQ + m0 + ql)) * SEQ + n0 + ch;
    const int4* mk4 = reinterpret_cast<const int4*>(mask + base);
    float4* dst = reinterpret_cast<float4*>(g_S + base);
#pragma unroll
    for (int j4 = 0; j4 < 8; j4++) {
        float4 v = *reinterpret_cast<const float4*>(&smf[ql * SF + ch + j4 * 4]);
        int4 mk = mk4[j4];
        v.x = mk.x ? v.x * scale : -INFINITY;
        v.y = mk.y ? v.y * scale : -INFINITY;
        v.z = mk.z ? v.z * scale : -INFINITY;
        v.w = mk.w ? v.w * scale : -INFINITY;
        dst[j4] = v;
    }
}

// ---------------------------------------------------------------------------
// Kernel 3: row softmax, fp32 in -> fp16 P out.  grid = B*S, block 256
// ---------------------------------------------------------------------------
__global__ void softmax_kernel() {
    const size_t row = (size_t)blockIdx.x * SEQ;
    const float* Srow = g_S + row;
    const int tid = threadIdx.x;

    float v[8];
    float m = -INFINITY;
#pragma unroll
    for (int i = 0; i < 8; i++) {
        v[i] = Srow[i * 256 + tid];
        m = fmaxf(m, v[i]);
    }
#pragma unroll
    for (int o = 16; o > 0; o >>= 1) m = fmaxf(m, __shfl_xor_sync(0xffffffffu, m, o));
    __shared__ float smax[8];
    if ((tid & 31) == 0) smax[tid >> 5] = m;
    __syncthreads();
    float mm = smax[0];
#pragma unroll
    for (int i = 1; i < 8; i++) mm = fmaxf(mm, smax[i]);

    float s = 0.f;
#pragma unroll
    for (int i = 0; i < 8; i++) { v[i] = __expf(v[i] - mm); s += v[i]; }
#pragma unroll
    for (int o = 16; o > 0; o >>= 1) s += __shfl_xor_sync(0xffffffffu, s, o);
    __shared__ float ssum[8];
    if ((tid & 31) == 0) ssum[tid >> 5] = s;
    __syncthreads();
    float tot = 0.f;
#pragma unroll
    for (int i = 0; i < 8; i++) tot += ssum[i];
    const float inv = 1.0f / tot;
#pragma unroll
    for (int i = 0; i < 8; i++)
        g_Pf[row + i * 256 + tid] = __float2half(v[i] * inv);
}

// ---------------------------------------------------------------------------
// Kernel 4: out = P @ V (fp16 single product).  grid = (H/64, SEQ/128, 4), 256
// ---------------------------------------------------------------------------
__global__ void __launch_bounds__(256, 2)
pv_kernel(float* __restrict__ out) {
    extern __shared__ char sm[];
    const uint32_t sbase = smem_to_u32(sm);
    const int tid = threadIdx.x;
    const int b = blockIdx.z;
    const int m0 = blockIdx.y * 128, n0 = blockIdx.x * 64;

    const size_t rowA = ((size_t)b * SEQ + m0) * SEQ;
    const size_t rowB = (size_t)b * H * SEQ + (size_t)n0 * SEQ;

    float acc[2][4][4] = {};
    gemm_core_1p(g_Pf + rowA, SEQ, g_Vtf + rowB, SEQ, SEQ, sbase, tid, acc);

    float* smf = reinterpret_cast<float*>(sm);
    acc_to_smem(acc, smf, tid);
    __syncthreads();

    const int row = tid >> 1, ch = (tid & 1) * 32;
    const size_t base = ((size_t)(b * SEQ + m0 + row)) * H + n0 + ch;
    float4* dst = reinterpret_cast<float4*>(out + base);
#pragma unroll
    for (int j4 = 0; j4 < 8; j4++)
        dst[j4] = *reinterpret_cast<const float4*>(&smf[row * SF + ch + j4 * 4]);
}

// ---------------------------------------------------------------------------
extern "C" void kernel_launch(void* const* d_in, const int* in_sizes, int n_in,
                              void* d_out, int out_size) {
    const float* x   = (const float*)d_in[0];
    const int*  mask = (const int*)  d_in[1];
    const float* Wq  = (const float*)d_in[2];
    const float* bq  = (const float*)d_in[3];
    const float* Wk  = (const float*)d_in[4];
    const float* bk  = (const float*)d_in[5];
    const float* Wv  = (const float*)d_in[6];
    const float* bv  = (const float*)d_in[7];
    float* out = (float*)d_out;

    cudaFuncSetAttribute(qkv_kernel,    cudaFuncAttributeMaxDynamicSharedMemorySize, SMEM_BYTES);
    cudaFuncSetAttribute(scores_kernel, cudaFuncAttributeMaxDynamicSharedMemorySize, SMEM_BYTES);
    cudaFuncSetAttribute(pv_kernel,     cudaFuncAttributeMaxDynamicSharedMemorySize, PV_SMEM_BYTES);

    __nv_bfloat16 *Xh, *Xl, *Wh, *Wl;
    cudaGetSymbolAddress((void**)&Xh, g_Xh);
    cudaGetSymbolAddress((void**)&Xl, g_Xl);
    cudaGetSymbolAddress((void**)&Wh, g_Wh);
    cudaGetSymbolAddress((void**)&Wl, g_Wl);

    const int n4x = M_ALL * H / 4;
    const int n4w = H * H / 4;
    split_kernel<<<n4x / 256, 256>>>(x, Xh, Xl, n4x);
    split_kernel<<<n4w / 256, 256>>>(Wq, Wh + 0 * (size_t)H * H, Wl + 0 * (size_t)H * H, n4w);
    split_kernel<<<n4w / 256, 256>>>(Wk, Wh + 1 * (size_t)H * H, Wl + 1 * (size_t)H * H, n4w);
    split_kernel<<<n4w / 256, 256>>>(Wv, Wh + 2 * (size_t)H * H, Wl + 2 * (size_t)H * H, n4w);

    qkv_kernel   <<<dim3(H / 64, M_ALL / 128, 3), 256, SMEM_BYTES>>>(bq, bk, bv);
    scores_kernel<<<dim3(SEQ / 64, SEQ / 128, BATCH), 256, SMEM_BYTES>>>(mask);
    softmax_kernel<<<BATCH * SEQ, 256>>>();
    pv_kernel    <<<dim3(H / 64, SEQ / 128, BATCH), 256, PV_SMEM_BYTES>>>(out);
}

// round 17
// speedup vs baseline: 1.5774x; 1.2301x over previous
#include <cuda_runtime.h>
#include <cuda_fp16.h>
#include <cstdint>
#include <math.h>

#define H       1024
#define BATCH   4
#define SEQ     2048
#define M_ALL   (BATCH * SEQ)

// ---------------------------------------------------------------------------
// Tiling: CTA 128x64, K-chunk 32, 8 warps (4 rows x 2 cols), warp tile 32x32.
// QKV/scores: fp16 2-product (A split hi/lo, B single).  PV: fp16 1-product.
// 3-stage cp.async pipeline, one __syncthreads per chunk, 2 CTAs/SM.
// ---------------------------------------------------------------------------
constexpr int RB          = 80;                 // smem bytes/row (64B data + 16B pad)
constexpr int TA_BYTES    = 128 * RB;           // 10240 (A tile: 128 rows)
constexpr int TB_BYTES    = 64 * RB;            // 5120  (B tile: 64 rows)
// 2-product layout: Ah, Al, B
constexpr int OFF2_AH     = 0;
constexpr int OFF2_AL     = TA_BYTES;
constexpr int OFF2_B      = 2 * TA_BYTES;
constexpr int STAGE2      = 2 * TA_BYTES + TB_BYTES;       // 25600
constexpr int NSTAGE      = 3;
constexpr int SMEM2       = NSTAGE * STAGE2;               // 76800 -> 2 CTAs/SM
// 1-product layout: A, B
constexpr int P_OFF_A       = 0;
constexpr int P_OFF_B       = TA_BYTES;
constexpr int P_STAGE_BYTES = TA_BYTES + TB_BYTES;         // 15360
constexpr int PV_SMEM_BYTES = NSTAGE * P_STAGE_BYTES;      // 46080 (epi needs 34816)
constexpr int SF          = 68;                 // epilogue f32 row stride (64+4)

// ---------------------------------------------------------------------------
// PTX helpers (sm_103 baseline ISA only: ldmatrix / mma.sync / cp.async)
// ---------------------------------------------------------------------------
__device__ __forceinline__ uint32_t smem_to_u32(const void* p) {
    uint32_t a;
    asm("{ .reg .u64 t; cvta.to.shared.u64 t, %1; cvt.u32.u64 %0, t; }" : "=r"(a) : "l"(p));
    return a;
}

#define CP_ASYNC16(dst, src) \
    asm volatile("cp.async.cg.shared.global [%0], [%1], 16;" :: "r"(dst), "l"(src))
#define CP_COMMIT() asm volatile("cp.async.commit_group;" ::: "memory")
#define CP_WAIT(n)  asm volatile("cp.async.wait_group %0;" :: "n"(n) : "memory")

#define LDSM_X4(r0, r1, r2, r3, addr) \
    asm volatile("ldmatrix.sync.aligned.m8n8.x4.shared.b16 {%0,%1,%2,%3}, [%4];" \
        : "=r"(r0), "=r"(r1), "=r"(r2), "=r"(r3) : "r"(addr))

__device__ __forceinline__ void mma16816h(float* c, const uint32_t* a,
                                          uint32_t b0, uint32_t b1) {
    asm volatile(
        "mma.sync.aligned.m16n8k16.row.col.f32.f16.f16.f32 "
        "{%0,%1,%2,%3}, {%4,%5,%6,%7}, {%8,%9}, {%0,%1,%2,%3};"
        : "+f"(c[0]), "+f"(c[1]), "+f"(c[2]), "+f"(c[3])
        : "r"(a[0]), "r"(a[1]), "r"(a[2]), "r"(a[3]), "r"(b0), "r"(b1));
}

// ---------------------------------------------------------------------------
// Scratch (device globals; allocation-free).  All operands fp16.
// ---------------------------------------------------------------------------
__device__ __align__(256) __half g_Xh[(size_t)M_ALL * H];
__device__ __align__(256) __half g_Xl[(size_t)M_ALL * H];
__device__ __align__(256) __half g_Wf[3 * (size_t)H * H];
__device__ __align__(256) __half g_Qh[(size_t)M_ALL * H];
__device__ __align__(256) __half g_Ql[(size_t)M_ALL * H];
__device__ __align__(256) __half g_Kf[(size_t)M_ALL * H];
__device__ __align__(256) __half g_Vtf[(size_t)BATCH * H * SEQ];   // [b][h][s]
__device__ __align__(256) float  g_S [(size_t)BATCH * SEQ * SEQ];
__device__ __align__(256) __half g_Pf[(size_t)BATCH * SEQ * SEQ];

// ---------------------------------------------------------------------------
// Stage loaders (256 threads).  A tile: 128 rows x 32 -> 2 copies/thread.
// B tile: 64 rows -> 1 copy/thread.
// ---------------------------------------------------------------------------
__device__ __forceinline__ void stage_A(const __half* __restrict__ g,
                                        size_t ld, int k0, uint32_t dst, int tid) {
#pragma unroll
    for (int i = 0; i < 2; i++) {
        int u = i * 256 + tid;
        int row = u >> 2, c = u & 3;
        CP_ASYNC16(dst + row * RB + c * 16, g + (size_t)row * ld + k0 + c * 8);
    }
}
__device__ __forceinline__ void stage_B(const __half* __restrict__ g,
                                        size_t ld, int k0, uint32_t dst, int tid) {
    const int row = tid >> 2, c = tid & 3;
    CP_ASYNC16(dst + row * RB + c * 16, g + (size_t)row * ld + k0 + c * 8);
}

__device__ __forceinline__ void stage_all_2p(const __half* Ah, const __half* Al,
                                             size_t lda, const __half* B, size_t ldb,
                                             int k0, uint32_t sb, int tid) {
    stage_A(Ah, lda, k0, sb + OFF2_AH, tid);
    stage_A(Al, lda, k0, sb + OFF2_AL, tid);
    stage_B(B,  ldb, k0, sb + OFF2_B,  tid);
    CP_COMMIT();
}
__device__ __forceinline__ void stage_all_1p(const __half* A, size_t lda,
                                             const __half* B, size_t ldb,
                                             int k0, uint32_t sb, int tid) {
    stage_A(A, lda, k0, sb + P_OFF_A, tid);
    stage_B(B, ldb, k0, sb + P_OFF_B, tid);
    CP_COMMIT();
}

// ---------------------------------------------------------------------------
// Compute one 32-wide K-chunk.
// 2p: C += (Ah + Al) * B   (2 products)
// ---------------------------------------------------------------------------
__device__ __forceinline__ void compute_stage_2p(uint32_t st_base, uint32_t aByte,
                                                 uint32_t bByte, float (&acc)[2][4][4]) {
#pragma unroll
    for (int ks = 0; ks < 2; ks++) {
        uint32_t ah[2][4], al[2][4], bh[2][4];
#pragma unroll
        for (int np = 0; np < 2; np++) {
            uint32_t bo = st_base + bByte + np * 16 * RB + ks * 32;
            LDSM_X4(bh[np][0], bh[np][1], bh[np][2], bh[np][3], bo + OFF2_B);
        }
#pragma unroll
        for (int mt = 0; mt < 2; mt++) {
            uint32_t ao = st_base + aByte + mt * 16 * RB + ks * 32;
            LDSM_X4(ah[mt][0], ah[mt][1], ah[mt][2], ah[mt][3], ao + OFF2_AH);
            LDSM_X4(al[mt][0], al[mt][1], al[mt][2], al[mt][3], ao + OFF2_AL);
        }
#pragma unroll
        for (int mt = 0; mt < 2; mt++)
#pragma unroll
            for (int nt = 0; nt < 4; nt++) {
                const uint32_t b0 = bh[nt >> 1][(nt & 1) * 2];
                const uint32_t b1 = bh[nt >> 1][(nt & 1) * 2 + 1];
                mma16816h(acc[mt][nt], ah[mt], b0, b1);
                mma16816h(acc[mt][nt], al[mt], b0, b1);
            }
    }
}
// 1p: C += A * B
__device__ __forceinline__ void compute_stage_1p(uint32_t st_base, uint32_t aByte,
                                                 uint32_t bByte, float (&acc)[2][4][4]) {
#pragma unroll
    for (int ks = 0; ks < 2; ks++) {
        uint32_t ah[2][4], bh[2][4];
#pragma unroll
        for (int np = 0; np < 2; np++) {
            uint32_t bo = st_base + bByte + np * 16 * RB + ks * 32;
            LDSM_X4(bh[np][0], bh[np][1], bh[np][2], bh[np][3], bo + P_OFF_B);
        }
#pragma unroll
        for (int mt = 0; mt < 2; mt++) {
            uint32_t ao = st_base + aByte + mt * 16 * RB + ks * 32;
            LDSM_X4(ah[mt][0], ah[mt][1], ah[mt][2], ah[mt][3], ao + P_OFF_A);
        }
#pragma unroll
        for (int mt = 0; mt < 2; mt++)
#pragma unroll
            for (int nt = 0; nt < 4; nt++) {
                const uint32_t b0 = bh[nt >> 1][(nt & 1) * 2];
                const uint32_t b1 = bh[nt >> 1][(nt & 1) * 2 + 1];
                mma16816h(acc[mt][nt], ah[mt], b0, b1);
            }
    }
}

// Per-lane ldmatrix base offsets
__device__ __forceinline__ uint32_t a_byte_off(uint32_t sbase, int wid, int lane) {
    const int wr = wid >> 1;
    return sbase + (uint32_t)((wr * 32 + (lane & 15)) * RB + (lane >> 4) * 16);
}
__device__ __forceinline__ uint32_t b_byte_off(uint32_t sbase, int wid, int lane) {
    const int wc = wid & 1;
    return sbase + (uint32_t)((wc * 32 + (lane & 7) + ((lane >> 4) & 1) * 8) * RB
                              + ((lane >> 3) & 1) * 16);
}

// ---------------------------------------------------------------------------
// Mainloops: 3-stage pipeline, prefetch distance 2, ONE __syncthreads/chunk.
// ---------------------------------------------------------------------------
__device__ __forceinline__ void gemm_core_2p(const __half* Ah, const __half* Al,
                                             size_t lda, const __half* B, size_t ldb,
                                             int Kdim, uint32_t sbase, int tid,
                                             float (&acc)[2][4][4]) {
    const int lane = tid & 31, wid = tid >> 5;
    const uint32_t aByte = a_byte_off(sbase, wid, lane);
    const uint32_t bByte = b_byte_off(sbase, wid, lane);

    const int nch = Kdim / 32;
    stage_all_2p(Ah, Al, lda, B, ldb, 0,  sbase + 0 * STAGE2, tid);
    stage_all_2p(Ah, Al, lda, B, ldb, 32, sbase + 1 * STAGE2, tid);

    int ld_stage = 2, cm_stage = 0;
#pragma unroll 1
    for (int c = 0; c < nch; c++) {
        CP_WAIT(1);
        __syncthreads();
        if (c + 2 < nch) {
            stage_all_2p(Ah, Al, lda, B, ldb, (c + 2) * 32,
                         sbase + (uint32_t)(ld_stage * STAGE2), tid);
        } else {
            CP_COMMIT();
        }
        ld_stage = (ld_stage == NSTAGE - 1) ? 0 : ld_stage + 1;
        compute_stage_2p((uint32_t)(cm_stage * STAGE2), aByte, bByte, acc);
        cm_stage = (cm_stage == NSTAGE - 1) ? 0 : cm_stage + 1;
    }
    CP_WAIT(0);
    __syncthreads();
}

__device__ __forceinline__ void gemm_core_1p(const __half* A, size_t lda,
                                             const __half* B, size_t ldb,
                                             int Kdim, uint32_t sbase, int tid,
                                             float (&acc)[2][4][4]) {
    const int lane = tid & 31, wid = tid >> 5;
    const uint32_t aByte = a_byte_off(sbase, wid, lane);
    const uint32_t bByte = b_byte_off(sbase, wid, lane);

    const int nch = Kdim / 32;
    stage_all_1p(A, lda, B, ldb, 0,  sbase + 0 * P_STAGE_BYTES, tid);
    stage_all_1p(A, lda, B, ldb, 32, sbase + 1 * P_STAGE_BYTES, tid);

    int ld_stage = 2, cm_stage = 0;
#pragma unroll 1
    for (int c = 0; c < nch; c++) {
        CP_WAIT(1);
        __syncthreads();
        if (c + 2 < nch) {
            stage_all_1p(A, lda, B, ldb, (c + 2) * 32,
                         sbase + (uint32_t)(ld_stage * P_STAGE_BYTES), tid);
        } else {
            CP_COMMIT();
        }
        ld_stage = (ld_stage == NSTAGE - 1) ? 0 : ld_stage + 1;
        compute_stage_1p((uint32_t)(cm_stage * P_STAGE_BYTES), aByte, bByte, acc);
        cm_stage = (cm_stage == NSTAGE - 1) ? 0 : cm_stage + 1;
    }
    CP_WAIT(0);
    __syncthreads();
}

// Scatter warp accumulators into a 128x64 f32 smem tile (stride SF)
__device__ __forceinline__ void acc_to_smem(float (&acc)[2][4][4], float* smf, int tid) {
    const int lane = tid & 31, wid = tid >> 5;
    const int wr = wid >> 1, wc = wid & 1;
    const int g = lane >> 2, t = lane & 3;
#pragma unroll
    for (int mt = 0; mt < 2; mt++)
#pragma unroll
        for (int nt = 0; nt < 4; nt++) {
            const int m = wr * 32 + mt * 16 + g;
            const int n = wc * 32 + nt * 8 + 2 * t;
            *reinterpret_cast<float2*>(&smf[m * SF + n]) =
                make_float2(acc[mt][nt][0], acc[mt][nt][1]);
            *reinterpret_cast<float2*>(&smf[(m + 8) * SF + n]) =
                make_float2(acc[mt][nt][2], acc[mt][nt][3]);
        }
}

// ---------------------------------------------------------------------------
// Prepass kernels: fp32 -> fp16 (hi, lo) split; fp32 -> fp16 convert
// ---------------------------------------------------------------------------
__global__ void split16_kernel(const float* __restrict__ src,
                               __half* __restrict__ dh,
                               __half* __restrict__ dl, int n4) {
    int i = blockIdx.x * blockDim.x + threadIdx.x;
    if (i >= n4) return;
    float4 v = reinterpret_cast<const float4*>(src)[i];
    float vv[4] = {v.x, v.y, v.z, v.w};
    __half hh[4], ll[4];
#pragma unroll
    for (int j = 0; j < 4; j++) {
        hh[j] = __float2half(vv[j]);
        ll[j] = __float2half(vv[j] - __half2float(hh[j]));
    }
    reinterpret_cast<__half2*>(dh)[2 * i]     = __halves2half2(hh[0], hh[1]);
    reinterpret_cast<__half2*>(dh)[2 * i + 1] = __halves2half2(hh[2], hh[3]);
    reinterpret_cast<__half2*>(dl)[2 * i]     = __halves2half2(ll[0], ll[1]);
    reinterpret_cast<__half2*>(dl)[2 * i + 1] = __halves2half2(ll[2], ll[3]);
}
__global__ void conv16_kernel(const float* __restrict__ src,
                              __half* __restrict__ d, int n4) {
    int i = blockIdx.x * blockDim.x + threadIdx.x;
    if (i >= n4) return;
    float4 v = reinterpret_cast<const float4*>(src)[i];
    reinterpret_cast<__half2*>(d)[2 * i]     = __halves2half2(__float2half(v.x), __float2half(v.y));
    reinterpret_cast<__half2*>(d)[2 * i + 1] = __halves2half2(__float2half(v.z), __float2half(v.w));
}

// ---------------------------------------------------------------------------
// Kernel 1: QKV projection.  z=0 -> Q (fp16 split), z=1 -> K (fp16), z=2 -> V^T
// grid = (H/64, M_ALL/128, 3), block = 256
// ---------------------------------------------------------------------------
__global__ void __launch_bounds__(256, 2)
qkv_kernel(const float* __restrict__ bq, const float* __restrict__ bk,
           const float* __restrict__ bv) {
    extern __shared__ char sm[];
    const uint32_t sbase = smem_to_u32(sm);
    const int tid = threadIdx.x;
    const int z = blockIdx.z;
    const int m0 = blockIdx.y * 128, n0 = blockIdx.x * 64;

    const __half* Ah = g_Xh + (size_t)m0 * H;
    const __half* Al = g_Xl + (size_t)m0 * H;
    const __half* B  = g_Wf + (size_t)z * H * H + (size_t)n0 * H;
    const float* bias = (z == 0) ? bq : (z == 1) ? bk : bv;

    float acc[2][4][4] = {};
    gemm_core_2p(Ah, Al, H, B, H, H, sbase, tid, acc);

    float* smf = reinterpret_cast<float*>(sm);
    acc_to_smem(acc, smf, tid);
    __syncthreads();

    if (z == 0) {
        const int row = tid >> 1, ch = (tid & 1) * 32;
        const size_t go = (size_t)(m0 + row) * H + n0 + ch;
#pragma unroll
        for (int q = 0; q < 4; q++) {
            uint32_t ph[4], pl[4];
#pragma unroll
            for (int j = 0; j < 4; j++) {
                const int n = ch + q * 8 + 2 * j;
                float c0 = smf[row * SF + n]     + bias[n0 + n];
                float c1 = smf[row * SF + n + 1] + bias[n0 + n + 1];
                __half h0 = __float2half(c0), h1 = __float2half(c1);
                __half l0 = __float2half(c0 - __half2float(h0));
                __half l1 = __float2half(c1 - __half2float(h1));
                __half2 vh = __halves2half2(h0, h1);
                __half2 vl = __halves2half2(l0, l1);
                ph[j] = *reinterpret_cast<uint32_t*>(&vh);
                pl[j] = *reinterpret_cast<uint32_t*>(&vl);
            }
            *reinterpret_cast<uint4*>(g_Qh + go + q * 8) = *reinterpret_cast<const uint4*>(ph);
            *reinterpret_cast<uint4*>(g_Ql + go + q * 8) = *reinterpret_cast<const uint4*>(pl);
        }
    } else if (z == 1) {
        const int row = tid >> 1, ch = (tid & 1) * 32;
        const size_t go = (size_t)(m0 + row) * H + n0 + ch;
#pragma unroll
        for (int q = 0; q < 4; q++) {
            uint32_t pk[4];
#pragma unroll
            for (int j = 0; j < 4; j++) {
                const int n = ch + q * 8 + 2 * j;
                float c0 = smf[row * SF + n]     + bias[n0 + n];
                float c1 = smf[row * SF + n + 1] + bias[n0 + n + 1];
                __half2 vk = __halves2half2(__float2half(c0), __float2half(c1));
                pk[j] = *reinterpret_cast<uint32_t*>(&vk);
            }
            *reinterpret_cast<uint4*>(g_Kf + go + q * 8) = *reinterpret_cast<const uint4*>(pk);
        }
    } else {
        // V transposed fp16: Vt[b][n][s]; threads map to s -> coalesced stores
        const int b = m0 >> 11;
        const int s0 = m0 & 2047;
        const int sl = tid & 127, nh = (tid >> 7) * 32;
#pragma unroll 1
        for (int j = 0; j < 32; j++) {
            const int nl = nh + j;
            float c = smf[sl * SF + nl] + bias[n0 + nl];
            const size_t a = (size_t)b * H * SEQ + (size_t)(n0 + nl) * SEQ + s0 + sl;
            g_Vtf[a] = __float2half(c);
        }
    }
}

// ---------------------------------------------------------------------------
// Kernel 2: scores S = mask ? (Q.K^T)/32 : -inf.  grid = (32, 16, 4), block 256
// ---------------------------------------------------------------------------
__global__ void __launch_bounds__(256, 2)
scores_kernel(const int* __restrict__ mask) {
    extern __shared__ char sm[];
    const uint32_t sbase = smem_to_u32(sm);
    const int tid = threadIdx.x;
    const int b = blockIdx.z;
    const int m0 = blockIdx.y * 128, n0 = blockIdx.x * 64;

    const size_t rowA = (size_t)(b * SEQ + m0) * H;
    const size_t rowB = (size_t)(b * SEQ + n0) * H;

    float acc[2][4][4] = {};
    gemm_core_2p(g_Qh + rowA, g_Ql + rowA, H, g_Kf + rowB, H, H, sbase, tid, acc);

    float* smf = reinterpret_cast<float*>(sm);
    acc_to_smem(acc, smf, tid);
    __syncthreads();

    const float scale = 0.03125f;  // 1/sqrt(1024)
    const int ql = tid >> 1, ch = (tid & 1) * 32;
    const size_t base = ((size_t)(b * SEQ + m0 + ql)) * SEQ + n0 + ch;
    const int4* mk4 = reinterpret_cast<const int4*>(mask + base);
    float4* dst = reinterpret_cast<float4*>(g_S + base);
#pragma unroll
    for (int j4 = 0; j4 < 8; j4++) {
        float4 v = *reinterpret_cast<const float4*>(&smf[ql * SF + ch + j4 * 4]);
        int4 mk = mk4[j4];
        v.x = mk.x ? v.x * scale : -INFINITY;
        v.y = mk.y ? v.y * scale : -INFINITY;
        v.z = mk.z ? v.z * scale : -INFINITY;
        v.w = mk.w ? v.w * scale : -INFINITY;
        dst[j4] = v;
    }
}

// ---------------------------------------------------------------------------
// Kernel 3: row softmax, fp32 in -> fp16 P out.  grid = B*S, block 256
// ---------------------------------------------------------------------------
__global__ void softmax_kernel() {
    const size_t row = (size_t)blockIdx.x * SEQ;
    const float* Srow = g_S + row;
    const int tid = threadIdx.x;

    float v[8];
    float m = -INFINITY;
#pragma unroll
    for (int i = 0; i < 8; i++) {
        v[i] = Srow[i * 256 + tid];
        m = fmaxf(m, v[i]);
    }
#pragma unroll
    for (int o = 16; o > 0; o >>= 1) m = fmaxf(m, __shfl_xor_sync(0xffffffffu, m, o));
    __shared__ float smax[8];
    if ((tid & 31) == 0) smax[tid >> 5] = m;
    __syncthreads();
    float mm = smax[0];
#pragma unroll
    for (int i = 1; i < 8; i++) mm = fmaxf(mm, smax[i]);

    float s = 0.f;
#pragma unroll
    for (int i = 0; i < 8; i++) { v[i] = __expf(v[i] - mm); s += v[i]; }
#pragma unroll
    for (int o = 16; o > 0; o >>= 1) s += __shfl_xor_sync(0xffffffffu, s, o);
    __shared__ float ssum[8];
    if ((tid & 31) == 0) ssum[tid >> 5] = s;
    __syncthreads();
    float tot = 0.f;
#pragma unroll
    for (int i = 0; i < 8; i++) tot += ssum[i];
    const float inv = 1.0f / tot;
#pragma unroll
    for (int i = 0; i < 8; i++)
        g_Pf[row + i * 256 + tid] = __float2half(v[i] * inv);
}

// ---------------------------------------------------------------------------
// Kernel 4: out = P @ V (fp16 1-product).  grid = (H/64, SEQ/128, 4), block 256
// ---------------------------------------------------------------------------
__global__ void __launch_bounds__(256, 2)
pv_kernel(float* __restrict__ out) {
    extern __shared__ char sm[];
    const uint32_t sbase = smem_to_u32(sm);
    const int tid = threadIdx.x;
    const int b = blockIdx.z;
    const int m0 = blockIdx.y * 128, n0 = blockIdx.x * 64;

    const size_t rowA = ((size_t)b * SEQ + m0) * SEQ;
    const size_t rowB = (size_t)b * H * SEQ + (size_t)n0 * SEQ;

    float acc[2][4][4] = {};
    gemm_core_1p(g_Pf + rowA, SEQ, g_Vtf + rowB, SEQ, SEQ, sbase, tid, acc);

    float* smf = reinterpret_cast<float*>(sm);
    acc_to_smem(acc, smf, tid);
    __syncthreads();

    const int row = tid >> 1, ch = (tid & 1) * 32;
    const size_t base = ((size_t)(b * SEQ + m0 + row)) * H + n0 + ch;
    float4* dst = reinterpret_cast<float4*>(out + base);
#pragma unroll
    for (int j4 = 0; j4 < 8; j4++)
        dst[j4] = *reinterpret_cast<const float4*>(&smf[row * SF + ch + j4 * 4]);
}

// ---------------------------------------------------------------------------
extern "C" void kernel_launch(void* const* d_in, const int* in_sizes, int n_in,
                              void* d_out, int out_size) {
    const float* x   = (const float*)d_in[0];
    const int*  mask = (const int*)  d_in[1];
    const float* Wq  = (const float*)d_in[2];
    const float* bq  = (const float*)d_in[3];
    const float* Wk  = (const float*)d_in[4];
    const float* bk  = (const float*)d_in[5];
    const float* Wv  = (const float*)d_in[6];
    const float* bv  = (const float*)d_in[7];
    float* out = (float*)d_out;

    cudaFuncSetAttribute(qkv_kernel,    cudaFuncAttributeMaxDynamicSharedMemorySize, SMEM2);
    cudaFuncSetAttribute(scores_kernel, cudaFuncAttributeMaxDynamicSharedMemorySize, SMEM2);
    cudaFuncSetAttribute(pv_kernel,     cudaFuncAttributeMaxDynamicSharedMemorySize, PV_SMEM_BYTES);

    __half *Xh, *Xl, *Wf;
    cudaGetSymbolAddress((void**)&Xh, g_Xh);
    cudaGetSymbolAddress((void**)&Xl, g_Xl);
    cudaGetSymbolAddress((void**)&Wf, g_Wf);

    const int n4x = M_ALL * H / 4;
    const int n4w = H * H / 4;
    split16_kernel<<<n4x / 256, 256>>>(x, Xh, Xl, n4x);
    conv16_kernel<<<n4w / 256, 256>>>(Wq, Wf + 0 * (size_t)H * H, n4w);
    conv16_kernel<<<n4w / 256, 256>>>(Wk, Wf + 1 * (size_t)H * H, n4w);
    conv16_kernel<<<n4w / 256, 256>>>(Wv, Wf + 2 * (size_t)H * H, n4w);

    qkv_kernel   <<<dim3(H / 64, M_ALL / 128, 3), 256, SMEM2>>>(bq, bk, bv);
    scores_kernel<<<dim3(SEQ / 64, SEQ / 128, BATCH), 256, SMEM2>>>(mask);
    softmax_kernel<<<BATCH * SEQ, 256>>>();
    pv_kernel    <<<dim3(H / 64, SEQ / 128, BATCH), 256, PV_SMEM_BYTES>>>(out);
}